// round 5
// baseline (speedup 1.0000x reference)
#include <cuda_runtime.h>
#include <cuda_bf16.h>
#include <cstdint>

#define BATCH    16
#define N_COARSE 1024
#define N_FINE   4096
#define C_IN     256
#define C_SKIP   128
#define C_HID    256
#define NC_TOT   (BATCH * N_COARSE)   // 16384
#define NF_TOT   (BATCH * N_FINE)     // 65536

// ---------------- scratch (static device globals; no runtime alloc) --------
__device__ float          g_y[NC_TOT * C_HID];                 // 16 MB fp32
__device__ int            g_idx[NF_TOT * 3];
__device__ float          g_w[NF_TOT * 3];
__device__ __nv_bfloat16  g_xe[NC_TOT * 2 * C_IN];             // [16384, 512]  [hi|lo]
__device__ __nv_bfloat16  g_xse[NF_TOT * 2 * C_SKIP];          // [65536, 256]  [hi|lo]
__device__ __nv_bfloat16  g_h1e[(size_t)NF_TOT * 2 * C_HID];   // [65536, 512]  [hi|lo]
__device__ __nv_bfloat16  g_w1ae[C_HID * 3 * C_IN];            // [256 n, 768 k] [hi|hi|lo]
__device__ __nv_bfloat16  g_w1be[C_HID * 3 * C_SKIP];          // [256 n, 384 k]
__device__ __nv_bfloat16  g_w2e[C_HID * 3 * C_HID];            // [256 n, 768 k]

// ---------------- PTX helpers (portable, no arch-gated features) -----------
__device__ __forceinline__ uint32_t smem_u32(const void* p) {
    return (uint32_t)__cvta_generic_to_shared(p);
}
__device__ __forceinline__ void cp16(uint32_t dst, const void* src) {
    asm volatile("cp.async.cg.shared.global [%0], [%1], 16;" :: "r"(dst), "l"(src));
}
#define CP_COMMIT()  asm volatile("cp.async.commit_group;" ::: "memory")
#define CP_WAIT(n)   asm volatile("cp.async.wait_group %0;" :: "n"(n) : "memory")
#define LDSM4(r, addr) \
    asm volatile("ldmatrix.sync.aligned.m8n8.x4.shared.b16 {%0,%1,%2,%3}, [%4];" \
        : "=r"((r)[0]), "=r"((r)[1]), "=r"((r)[2]), "=r"((r)[3]) : "r"(addr))

__device__ __forceinline__ void mma16816(float* c, const uint32_t* a, const uint32_t* b) {
    asm volatile(
        "mma.sync.aligned.m16n8k16.row.col.f32.bf16.bf16.f32 "
        "{%0,%1,%2,%3}, {%4,%5,%6,%7}, {%8,%9}, {%0,%1,%2,%3};"
        : "+f"(c[0]), "+f"(c[1]), "+f"(c[2]), "+f"(c[3])
        : "r"(a[0]), "r"(a[1]), "r"(a[2]), "r"(a[3]), "r"(b[0]), "r"(b[1]));
}

// ---------------- kNN (k=3): float4 smem, 2 fine points per thread ---------
#define KNN_TPB 128
#define KNN_PPB 256     // fine points per block

__global__ __launch_bounds__(KNN_TPB) void knn_kernel(
    const float* __restrict__ pos, const float* __restrict__ pos_skip,
    int* __restrict__ gidx, float* __restrict__ gw)
{
    __shared__ float4 sp[N_COARSE];   // 16 KB
    const int bpc = N_FINE / KNN_PPB;               // 16 blocks per cloud
    const int b = blockIdx.x / bpc;
    const int chunk = blockIdx.x % bpc;
    const int tid = threadIdx.x;

    const float* pc = pos + (size_t)b * N_COARSE * 3;
    for (int i = tid; i < N_COARSE; i += KNN_TPB)
        sp[i] = make_float4(pc[i * 3 + 0], pc[i * 3 + 1], pc[i * 3 + 2], 0.f);
    __syncthreads();

    const int fbase = b * N_FINE + chunk * KNN_PPB;
    const int fA = fbase + tid;
    const int fB = fbase + KNN_TPB + tid;

    const float ax = pos_skip[fA * 3 + 0], ay = pos_skip[fA * 3 + 1], az = pos_skip[fA * 3 + 2];
    const float bx = pos_skip[fB * 3 + 0], by = pos_skip[fB * 3 + 1], bz = pos_skip[fB * 3 + 2];

    float a0 = 3.4e38f, a1 = 3.4e38f, a2 = 3.4e38f;
    float c0 = 3.4e38f, c1 = 3.4e38f, c2 = 3.4e38f;
    int ai0 = 0, ai1 = 0, ai2 = 0, ci0 = 0, ci1 = 0, ci2 = 0;

    #pragma unroll 2
    for (int j = 0; j < N_COARSE; j++) {
        float4 p = sp[j];
        float dax = ax - p.x, day = ay - p.y, daz = az - p.z;
        float da = dax * dax + day * day + daz * daz;
        float dbx = bx - p.x, dby = by - p.y, dbz = bz - p.z;
        float db = dbx * dbx + dby * dby + dbz * dbz;
        if (da < a2) {
            if (da < a1) {
                a2 = a1; ai2 = ai1;
                if (da < a0) { a1 = a0; ai1 = ai0; a0 = da; ai0 = j; }
                else         { a1 = da; ai1 = j; }
            } else { a2 = da; ai2 = j; }
        }
        if (db < c2) {
            if (db < c1) {
                c2 = c1; ci2 = ci1;
                if (db < c0) { c1 = c0; ci1 = ci0; c0 = db; ci0 = j; }
                else         { c1 = db; ci1 = j; }
            } else { c2 = db; ci2 = j; }
        }
    }

    {
        float w0 = 1.0f / fmaxf(a0, 1e-16f);
        float w1 = 1.0f / fmaxf(a1, 1e-16f);
        float w2 = 1.0f / fmaxf(a2, 1e-16f);
        float inv = 1.0f / (w0 + w1 + w2);
        gidx[fA * 3 + 0] = b * N_COARSE + ai0;
        gidx[fA * 3 + 1] = b * N_COARSE + ai1;
        gidx[fA * 3 + 2] = b * N_COARSE + ai2;
        gw[fA * 3 + 0] = w0 * inv; gw[fA * 3 + 1] = w1 * inv; gw[fA * 3 + 2] = w2 * inv;
    }
    {
        float w0 = 1.0f / fmaxf(c0, 1e-16f);
        float w1 = 1.0f / fmaxf(c1, 1e-16f);
        float w2 = 1.0f / fmaxf(c2, 1e-16f);
        float inv = 1.0f / (w0 + w1 + w2);
        gidx[fB * 3 + 0] = b * N_COARSE + ci0;
        gidx[fB * 3 + 1] = b * N_COARSE + ci1;
        gidx[fB * 3 + 2] = b * N_COARSE + ci2;
        gw[fB * 3 + 0] = w0 * inv; gw[fB * 3 + 1] = w1 * inv; gw[fB * 3 + 2] = w2 * inv;
    }
}

// ---------------- split-bf16 expansion --------------------------------------
// activations: [M,K] fp32 -> [M,2K] bf16 segments [hi | lo] (vectorized x2)
__global__ void expand_act(const float* __restrict__ in, __nv_bfloat16* __restrict__ out,
                           int M, int K)
{
    int i = blockIdx.x * blockDim.x + threadIdx.x;      // pair index
    int tot = M * (K / 2);
    if (i >= tot) return;
    int kh = K / 2;
    int m = i / kh, kp = i - m * kh;
    float2 v = *(const float2*)(in + (size_t)m * K + kp * 2);
    __nv_bfloat16 hx = __float2bfloat16(v.x), hy = __float2bfloat16(v.y);
    __nv_bfloat162 hi2 = __halves2bfloat162(hx, hy);
    __nv_bfloat162 lo2 = __halves2bfloat162(
        __float2bfloat16(v.x - __bfloat162float(hx)),
        __float2bfloat16(v.y - __bfloat162float(hy)));
    __nv_bfloat16* o = out + (size_t)m * 2 * K + kp * 2;
    *(__nv_bfloat162*)(o)     = hi2;
    *(__nv_bfloat162*)(o + K) = lo2;
}
// all weights in one launch; output transposed [N, 3K] bf16, segs [hi|hi|lo]
__global__ void expand_w_all(const float* __restrict__ W1, const float* __restrict__ W2,
                             __nv_bfloat16* __restrict__ w1ae,
                             __nv_bfloat16* __restrict__ w1be,
                             __nv_bfloat16* __restrict__ w2e)
{
    int i = blockIdx.x * blockDim.x + threadIdx.x;
    const int TOT1 = (C_IN + C_SKIP) * C_HID;     // 98304
    const int TOT2 = C_HID * C_HID;               // 65536
    if (i >= TOT1 + TOT2) return;
    float v; __nv_bfloat16* o; int K, k, n;
    if (i < TOT1) {
        k = i / C_HID; n = i - k * C_HID;
        v = W1[i];
        if (k < C_IN) { K = C_IN; o = w1ae + (size_t)n * 3 * K; }
        else          { K = C_SKIP; k -= C_IN; o = w1be + (size_t)n * 3 * K; }
    } else {
        int j = i - TOT1;
        k = j / C_HID; n = j - k * C_HID;
        v = W2[j];
        K = C_HID; o = w2e + (size_t)n * 3 * K;
    }
    __nv_bfloat16 hi = __float2bfloat16(v);
    __nv_bfloat16 lo = __float2bfloat16(v - __bfloat162float(hi));
    o[k] = hi; o[K + k] = hi; o[2 * K + k] = lo;
}

// ---------------- HMMA GEMM (3-stage cp.async + ldmatrix) -------------------
// C[128,128] per CTA.  A:[M,2K] bf16 [hi|lo] (hi chunks re-read for seg 3),
// Bw:[N,3K] bf16 [hi|hi|lo].  256 thr = 8 warps (4x2); warp tile 32x64; BK=32.
// MODE 0: store fp32   MODE 1: bias+gather+relu -> [hi|lo] bf16 h1e
// MODE 2: bias+relu -> fp32
#define PITCH 40                        // bf16 per smem row (80B)
#define OP_BYTES (128 * PITCH * 2)      // 10240 per operand per stage
#define STAGE_BYTES (2 * OP_BYTES)      // 20480
#define SM_BYTES (3 * STAGE_BYTES)      // 61440

template <int MODE>
__global__ __launch_bounds__(256, 2) void mma_gemm(
    const __nv_bfloat16* __restrict__ A, const __nv_bfloat16* __restrict__ Bw,
    const float* __restrict__ bias, float* __restrict__ outf,
    __nv_bfloat16* __restrict__ outh, int ldA, int ldB, int nchunks, int two_nh,
    const float* __restrict__ Y, const int* __restrict__ gidx,
    const float* __restrict__ gw)
{
    extern __shared__ __align__(16) char smem[];
    const uint32_t sb = smem_u32(smem);

    const int tid = threadIdx.x;
    const int wid = tid >> 5, lane = tid & 31;
    const int g = lane >> 2, t = lane & 3;
    const int wm = wid & 3, wn = wid >> 2;        // 4 x 2 warp grid
    const int row0 = blockIdx.y * 128, col0 = blockIdx.x * 128;

    // cp.async loader: 128 rows x 32 bf16 (64B) per operand per stage
    const int lrow = tid >> 1;                    // 0..127
    const int lch  = (tid & 1) * 2;               // 16B-chunk 0 or 2
    const uint32_t dA0 = sb + (uint32_t)(lrow * 80 + lch * 16);
    const uint32_t dB0 = dA0 + OP_BYTES;
    const __nv_bfloat16* gA = A + (size_t)(row0 + lrow) * ldA + lch * 8;
    const __nv_bfloat16* gB = Bw + (size_t)(col0 + lrow) * ldB + lch * 8;

    // ldmatrix base addresses (stage 0)
    uint32_t aAddr[2], bAddr[4];
    #pragma unroll
    for (int mt = 0; mt < 2; mt++)
        aAddr[mt] = sb + (uint32_t)(((wm * 32 + mt * 16 + (lane & 15)) * PITCH
                                     + (lane >> 4) * 8) * 2);
    #pragma unroll
    for (int p = 0; p < 4; p++)
        bAddr[p] = sb + OP_BYTES + (uint32_t)(((wn * 64 + p * 16 + (lane & 7)
                                     + ((lane >> 4) & 1) * 8) * PITCH
                                     + ((lane >> 3) & 1) * 8) * 2);

    float acc[2][8][4];
    #pragma unroll
    for (int mt = 0; mt < 2; mt++)
        #pragma unroll
        for (int nt = 0; nt < 8; nt++)
            #pragma unroll
            for (int e = 0; e < 4; e++) acc[mt][nt][e] = 0.f;

    // prologue: stages 0 and 1 (chunks 0,1 are always < two_nh)
    #pragma unroll
    for (int s = 0; s < 2; s++) {
        const int k0 = s * 32;
        const uint32_t dA = dA0 + s * STAGE_BYTES;
        const uint32_t dB = dB0 + s * STAGE_BYTES;
        cp16(dA, gA + k0); cp16(dA + 16, gA + k0 + 8);
        cp16(dB, gB + k0); cp16(dB + 16, gB + k0 + 8);
        CP_COMMIT();
    }

    int stage = 0, pstage = 2;
    for (int c = 0; c < nchunks; c++) {
        if (c + 1 == nchunks) { CP_WAIT(0); } else { CP_WAIT(1); }
        __syncthreads();

        if (c + 2 < nchunks) {
            const int c2 = c + 2;
            const int kA = ((c2 < two_nh) ? c2 : (c2 - two_nh)) * 32;
            const int kB = c2 * 32;
            const uint32_t dA = dA0 + pstage * STAGE_BYTES;
            const uint32_t dB = dB0 + pstage * STAGE_BYTES;
            cp16(dA, gA + kA); cp16(dA + 16, gA + kA + 8);
            cp16(dB, gB + kB); cp16(dB + 16, gB + kB + 8);
            CP_COMMIT();
            pstage = (pstage == 2) ? 0 : pstage + 1;
        }

        const uint32_t so = stage * STAGE_BYTES;
        #pragma unroll
        for (int ks = 0; ks < 2; ks++) {
            const uint32_t ko = so + ks * 32;     // 16 bf16 = 32 bytes
            uint32_t a[2][4], bq[4][4];
            LDSM4(a[0], aAddr[0] + ko);
            LDSM4(a[1], aAddr[1] + ko);
            LDSM4(bq[0], bAddr[0] + ko);
            LDSM4(bq[1], bAddr[1] + ko);
            LDSM4(bq[2], bAddr[2] + ko);
            LDSM4(bq[3], bAddr[3] + ko);
            #pragma unroll
            for (int mt = 0; mt < 2; mt++)
                #pragma unroll
                for (int nt = 0; nt < 8; nt++)
                    mma16816(acc[mt][nt], a[mt], &bq[nt >> 1][(nt & 1) * 2]);
        }
        stage = (stage == 2) ? 0 : stage + 1;
    }

    // ---- epilogue: registers -> global ----
    #pragma unroll
    for (int mt = 0; mt < 2; mt++) {
        #pragma unroll
        for (int half = 0; half < 2; half++) {
            const int r = row0 + wm * 32 + mt * 16 + g + half * 8;
            int i0 = 0, i1 = 0, i2 = 0;
            float w0 = 0.f, w1 = 0.f, w2 = 0.f;
            if (MODE == 1) {
                i0 = gidx[r * 3 + 0]; i1 = gidx[r * 3 + 1]; i2 = gidx[r * 3 + 2];
                w0 = gw[r * 3 + 0]; w1 = gw[r * 3 + 1]; w2 = gw[r * 3 + 2];
            }
            #pragma unroll
            for (int nt = 0; nt < 8; nt++) {
                const int ccol = col0 + wn * 64 + nt * 8 + 2 * t;
                float vx = acc[mt][nt][half * 2 + 0];
                float vy = acc[mt][nt][half * 2 + 1];
                if (MODE == 0) {
                    *(float2*)&outf[(size_t)r * C_HID + ccol] = make_float2(vx, vy);
                } else if (MODE == 2) {
                    float2 bb = *(const float2*)&bias[ccol];
                    vx = fmaxf(vx + bb.x, 0.f);
                    vy = fmaxf(vy + bb.y, 0.f);
                    *(float2*)&outf[(size_t)r * C_HID + ccol] = make_float2(vx, vy);
                } else {
                    float2 bb = *(const float2*)&bias[ccol];
                    float2 y0 = *(const float2*)&Y[(size_t)i0 * C_HID + ccol];
                    float2 y1 = *(const float2*)&Y[(size_t)i1 * C_HID + ccol];
                    float2 y2 = *(const float2*)&Y[(size_t)i2 * C_HID + ccol];
                    vx = fmaxf(vx + bb.x + w0 * y0.x + w1 * y1.x + w2 * y2.x, 0.f);
                    vy = fmaxf(vy + bb.y + w0 * y0.y + w1 * y1.y + w2 * y2.y, 0.f);
                    __nv_bfloat16 hx = __float2bfloat16(vx);
                    __nv_bfloat16 hy = __float2bfloat16(vy);
                    __nv_bfloat162 hi2 = __halves2bfloat162(hx, hy);
                    __nv_bfloat162 lo2 = __halves2bfloat162(
                        __float2bfloat16(vx - __bfloat162float(hx)),
                        __float2bfloat16(vy - __bfloat162float(hy)));
                    const size_t base = (size_t)r * (2 * C_HID) + ccol;
                    *(__nv_bfloat162*)&outh[base]         = hi2;
                    *(__nv_bfloat162*)&outh[base + C_HID] = lo2;
                }
            }
        }
    }
}

// batch_skip int32 -> float (tuple tail)
__global__ void cast_batch_kernel(const int* __restrict__ b, float* __restrict__ out, int n)
{
    int i = blockIdx.x * blockDim.x + threadIdx.x;
    if (i < n) out[i] = (float)b[i];
}

// ---------------------------------------------------------------------------
extern "C" void kernel_launch(void* const* d_in, const int* in_sizes, int n_in,
                              void* d_out, int out_size)
{
    (void)in_sizes; (void)n_in;
    const float* x        = (const float*)d_in[0];
    const float* pos      = (const float*)d_in[1];
    const float* x_skip   = (const float*)d_in[2];
    const float* pos_skip = (const float*)d_in[3];
    const float* W1       = (const float*)d_in[4];
    const float* b1       = (const float*)d_in[5];
    const float* W2       = (const float*)d_in[6];
    const float* b2       = (const float*)d_in[7];

    float *y, *w; int* idx;
    __nv_bfloat16 *xe, *xse, *h1e, *w1ae, *w1be, *w2e;
    cudaGetSymbolAddress((void**)&y,    g_y);
    cudaGetSymbolAddress((void**)&idx,  g_idx);
    cudaGetSymbolAddress((void**)&w,    g_w);
    cudaGetSymbolAddress((void**)&xe,   g_xe);
    cudaGetSymbolAddress((void**)&xse,  g_xse);
    cudaGetSymbolAddress((void**)&h1e,  g_h1e);
    cudaGetSymbolAddress((void**)&w1ae, g_w1ae);
    cudaGetSymbolAddress((void**)&w1be, g_w1be);
    cudaGetSymbolAddress((void**)&w2e,  g_w2e);

    static bool attr_done = false;
    if (!attr_done) {
        cudaFuncSetAttribute(mma_gemm<0>, cudaFuncAttributeMaxDynamicSharedMemorySize, SM_BYTES);
        cudaFuncSetAttribute(mma_gemm<1>, cudaFuncAttributeMaxDynamicSharedMemorySize, SM_BYTES);
        cudaFuncSetAttribute(mma_gemm<2>, cudaFuncAttributeMaxDynamicSharedMemorySize, SM_BYTES);
        attr_done = true;
    }

    // expansions + knn
    expand_act<<<(NC_TOT * C_IN / 2 + 255) / 256, 256>>>(x, xe, NC_TOT, C_IN);
    expand_act<<<(NF_TOT * C_SKIP / 2 + 255) / 256, 256>>>(x_skip, xse, NF_TOT, C_SKIP);
    expand_w_all<<<((C_IN + C_SKIP + C_HID) * C_HID + 255) / 256, 256>>>(
        W1, W2, w1ae, w1be, w2e);
    knn_kernel<<<BATCH * (N_FINE / KNN_PPB), KNN_TPB>>>(pos, pos_skip, idx, w);

    // GEMM1: y = x @ W1a    A [16384,512], B [256,768], 24 chunks, two_nh=16
    mma_gemm<0><<<dim3(2, NC_TOT / 128), 256, SM_BYTES>>>(
        xe, w1ae, nullptr, y, nullptr, 2 * C_IN, 3 * C_IN, (3 * C_IN) / 32,
        (2 * C_IN) / 32, nullptr, nullptr, nullptr);

    // GEMM2: h1 = relu(x_skip @ W1b + interp(y) + b1) -> [hi|lo] bf16 h1e
    mma_gemm<1><<<dim3(2, NF_TOT / 128), 256, SM_BYTES>>>(
        xse, w1be, b1, nullptr, h1e, 2 * C_SKIP, 3 * C_SKIP, (3 * C_SKIP) / 32,
        (2 * C_SKIP) / 32, y, idx, w);

    // GEMM3: out = relu(h1 @ W2 + b2) -> fp32 d_out
    mma_gemm<2><<<dim3(2, NF_TOT / 128), 256, SM_BYTES>>>(
        h1e, w2e, b2, (float*)d_out, nullptr, 2 * C_HID, 3 * C_HID, (3 * C_HID) / 32,
        (2 * C_HID) / 32, nullptr, nullptr, nullptr);

    // Tuple tail: (h, pos_skip, batch_skip) — append if the harness expects it
    const long long H_ELEMS   = (long long)NF_TOT * C_HID;
    const long long POS_ELEMS = (long long)NF_TOT * 3;
    if ((long long)out_size >= H_ELEMS + POS_ELEMS) {
        cudaMemcpyAsync((float*)d_out + H_ELEMS, pos_skip,
                        POS_ELEMS * sizeof(float), cudaMemcpyDeviceToDevice);
    }
    if ((long long)out_size >= H_ELEMS + POS_ELEMS + NF_TOT) {
        const int* batch_skip = (const int*)d_in[9];
        cast_batch_kernel<<<(NF_TOT + 255) / 256, 256>>>(
            batch_skip, (float*)d_out + H_ELEMS + POS_ELEMS, NF_TOT);
    }
}

// round 6
// speedup vs baseline: 1.2193x; 1.2193x over previous
#include <cuda_runtime.h>
#include <cuda_bf16.h>
#include <cstdint>

#define BATCH    16
#define N_COARSE 1024
#define N_FINE   4096
#define C_IN     256
#define C_SKIP   128
#define C_HID    256
#define NC_TOT   (BATCH * N_COARSE)   // 16384
#define NF_TOT   (BATCH * N_FINE)     // 65536

// ---------------- scratch (static device globals; no runtime alloc) --------
__device__ float          g_y[NC_TOT * C_HID];                 // 16 MB fp32
__device__ int            g_idx[NF_TOT * 3];
__device__ float          g_w[NF_TOT * 3];
__device__ __nv_bfloat16  g_xe[NC_TOT * 2 * C_IN];             // [16384, 512]  [hi|lo]
__device__ __nv_bfloat16  g_xse[NF_TOT * 2 * C_SKIP];          // [65536, 256]  [hi|lo]
__device__ __nv_bfloat16  g_h1e[(size_t)NF_TOT * 2 * C_HID];   // [65536, 512]  [hi|lo]
__device__ __nv_bfloat16  g_w1ae[C_HID * 3 * C_IN];            // [256 n, 768 k] [hi|hi|lo]
__device__ __nv_bfloat16  g_w1be[C_HID * 3 * C_SKIP];          // [256 n, 384 k]
__device__ __nv_bfloat16  g_w2e[C_HID * 3 * C_HID];            // [256 n, 768 k]

// ---------------- PTX helpers (portable, no arch-gated features) -----------
__device__ __forceinline__ uint32_t smem_u32(const void* p) {
    return (uint32_t)__cvta_generic_to_shared(p);
}
__device__ __forceinline__ void cp16(uint32_t dst, const void* src) {
    asm volatile("cp.async.cg.shared.global [%0], [%1], 16;" :: "r"(dst), "l"(src));
}
#define CP_COMMIT()  asm volatile("cp.async.commit_group;" ::: "memory")
#define CP_WAIT(n)   asm volatile("cp.async.wait_group %0;" :: "n"(n) : "memory")
#define LDSM4(r, addr) \
    asm volatile("ldmatrix.sync.aligned.m8n8.x4.shared.b16 {%0,%1,%2,%3}, [%4];" \
        : "=r"((r)[0]), "=r"((r)[1]), "=r"((r)[2]), "=r"((r)[3]) : "r"(addr))

__device__ __forceinline__ void mma16816(float* c, const uint32_t* a, const uint32_t* b) {
    asm volatile(
        "mma.sync.aligned.m16n8k16.row.col.f32.bf16.bf16.f32 "
        "{%0,%1,%2,%3}, {%4,%5,%6,%7}, {%8,%9}, {%0,%1,%2,%3};"
        : "+f"(c[0]), "+f"(c[1]), "+f"(c[2]), "+f"(c[3])
        : "r"(a[0]), "r"(a[1]), "r"(a[2]), "r"(a[3]), "r"(b[0]), "r"(b[1]));
}

// ---------------- kNN (k=3): 1 point/thread, float4 smem --------------------
__global__ __launch_bounds__(128) void knn_kernel(
    const float* __restrict__ pos, const float* __restrict__ pos_skip,
    int* __restrict__ gidx, float* __restrict__ gw)
{
    __shared__ float4 sp[N_COARSE];   // 16 KB
    const int chunks = N_FINE / 128;              // 32
    const int b = blockIdx.x / chunks;
    const int chunk = blockIdx.x % chunks;
    const int tid = threadIdx.x;

    const float* pc = pos + (size_t)b * N_COARSE * 3;
    for (int i = tid; i < N_COARSE; i += 128)
        sp[i] = make_float4(pc[i * 3 + 0], pc[i * 3 + 1], pc[i * 3 + 2], 0.f);
    __syncthreads();

    const int f = b * N_FINE + chunk * 128 + tid;
    const float px = pos_skip[f * 3 + 0];
    const float py = pos_skip[f * 3 + 1];
    const float pz = pos_skip[f * 3 + 2];

    float d0 = 3.4e38f, d1 = 3.4e38f, d2 = 3.4e38f;
    int i0 = 0, i1 = 0, i2 = 0;
    #pragma unroll 4
    for (int j = 0; j < N_COARSE; j++) {
        float4 p = sp[j];
        float dx = px - p.x, dy = py - p.y, dz = pz - p.z;
        float d = dx * dx + dy * dy + dz * dz;
        if (d < d2) {
            if (d < d1) {
                d2 = d1; i2 = i1;
                if (d < d0) { d1 = d0; i1 = i0; d0 = d; i0 = j; }
                else        { d1 = d;  i1 = j; }
            } else { d2 = d; i2 = j; }
        }
    }
    float w0 = 1.0f / fmaxf(d0, 1e-16f);
    float w1 = 1.0f / fmaxf(d1, 1e-16f);
    float w2 = 1.0f / fmaxf(d2, 1e-16f);
    float inv = 1.0f / (w0 + w1 + w2);
    gidx[f * 3 + 0] = b * N_COARSE + i0;
    gidx[f * 3 + 1] = b * N_COARSE + i1;
    gidx[f * 3 + 2] = b * N_COARSE + i2;
    gw[f * 3 + 0] = w0 * inv;
    gw[f * 3 + 1] = w1 * inv;
    gw[f * 3 + 2] = w2 * inv;
}

// ---------------- split-bf16 expansion --------------------------------------
// activations: [M,K] fp32 -> [M,2K] bf16 segments [hi | lo] (vectorized x2)
__global__ void expand_act(const float* __restrict__ in, __nv_bfloat16* __restrict__ out,
                           int M, int K)
{
    int i = blockIdx.x * blockDim.x + threadIdx.x;      // pair index
    int tot = M * (K / 2);
    if (i >= tot) return;
    int kh = K / 2;
    int m = i / kh, kp = i - m * kh;
    float2 v = *(const float2*)(in + (size_t)m * K + kp * 2);
    __nv_bfloat16 hx = __float2bfloat16(v.x), hy = __float2bfloat16(v.y);
    __nv_bfloat162 hi2 = __halves2bfloat162(hx, hy);
    __nv_bfloat162 lo2 = __halves2bfloat162(
        __float2bfloat16(v.x - __bfloat162float(hx)),
        __float2bfloat16(v.y - __bfloat162float(hy)));
    __nv_bfloat16* o = out + (size_t)m * 2 * K + kp * 2;
    *(__nv_bfloat162*)(o)     = hi2;
    *(__nv_bfloat162*)(o + K) = lo2;
}
// all weights in one launch; output transposed [N, 3K] bf16, segs [hi|hi|lo]
__global__ void expand_w_all(const float* __restrict__ W1, const float* __restrict__ W2,
                             __nv_bfloat16* __restrict__ w1ae,
                             __nv_bfloat16* __restrict__ w1be,
                             __nv_bfloat16* __restrict__ w2e)
{
    int i = blockIdx.x * blockDim.x + threadIdx.x;
    const int TOT1 = (C_IN + C_SKIP) * C_HID;     // 98304
    const int TOT2 = C_HID * C_HID;               // 65536
    if (i >= TOT1 + TOT2) return;
    float v; __nv_bfloat16* o; int K, k, n;
    if (i < TOT1) {
        k = i / C_HID; n = i - k * C_HID;
        v = W1[i];
        if (k < C_IN) { K = C_IN; o = w1ae + (size_t)n * 3 * K; }
        else          { K = C_SKIP; k -= C_IN; o = w1be + (size_t)n * 3 * K; }
    } else {
        int j = i - TOT1;
        k = j / C_HID; n = j - k * C_HID;
        v = W2[j];
        K = C_HID; o = w2e + (size_t)n * 3 * K;
    }
    __nv_bfloat16 hi = __float2bfloat16(v);
    __nv_bfloat16 lo = __float2bfloat16(v - __bfloat162float(hi));
    o[k] = hi; o[K + k] = hi; o[2 * K + k] = lo;
}

// ---------------- HMMA GEMM (3-stage cp.async + ldmatrix) -------------------
// C[128,128] per CTA.  A:[M,2K] bf16 [hi|lo] (hi chunks re-read for seg 3),
// Bw:[N,3K] bf16 [hi|hi|lo].  256 thr = 8 warps (4x2); warp tile 32x64; BK=32.
// MODE 0: store fp32   MODE 1: bias+gather+relu -> [hi|lo] bf16 h1e
// MODE 2: bias+relu -> fp32
#define PITCH 40                        // bf16 per smem row (80B)
#define OP_BYTES (128 * PITCH * 2)      // 10240 per operand per stage
#define STAGE_BYTES (2 * OP_BYTES)      // 20480
#define SM_BYTES (3 * STAGE_BYTES)      // 61440

template <int MODE>
__global__ __launch_bounds__(256, 2) void mma_gemm(
    const __nv_bfloat16* __restrict__ A, const __nv_bfloat16* __restrict__ Bw,
    const float* __restrict__ bias, float* __restrict__ outf,
    __nv_bfloat16* __restrict__ outh, int ldA, int ldB, int nchunks, int two_nh,
    const float* __restrict__ Y, const int* __restrict__ gidx,
    const float* __restrict__ gw)
{
    extern __shared__ __align__(16) char smem[];
    const uint32_t sb = smem_u32(smem);

    const int tid = threadIdx.x;
    const int wid = tid >> 5, lane = tid & 31;
    const int g = lane >> 2, t = lane & 3;
    const int wm = wid & 3, wn = wid >> 2;        // 4 x 2 warp grid
    const int row0 = blockIdx.y * 128, col0 = blockIdx.x * 128;

    // cp.async loader: 128 rows x 32 bf16 (64B) per operand per stage
    const int lrow = tid >> 1;                    // 0..127
    const int lch  = (tid & 1) * 2;               // 16B-chunk 0 or 2
    const uint32_t dA0 = sb + (uint32_t)(lrow * 80 + lch * 16);
    const uint32_t dB0 = dA0 + OP_BYTES;
    const __nv_bfloat16* gA = A + (size_t)(row0 + lrow) * ldA + lch * 8;
    const __nv_bfloat16* gB = Bw + (size_t)(col0 + lrow) * ldB + lch * 8;

    // ldmatrix base addresses (stage 0)
    uint32_t aAddr[2], bAddr[4];
    #pragma unroll
    for (int mt = 0; mt < 2; mt++)
        aAddr[mt] = sb + (uint32_t)(((wm * 32 + mt * 16 + (lane & 15)) * PITCH
                                     + (lane >> 4) * 8) * 2);
    #pragma unroll
    for (int p = 0; p < 4; p++)
        bAddr[p] = sb + OP_BYTES + (uint32_t)(((wn * 64 + p * 16 + (lane & 7)
                                     + ((lane >> 4) & 1) * 8) * PITCH
                                     + ((lane >> 3) & 1) * 8) * 2);

    float acc[2][8][4];
    #pragma unroll
    for (int mt = 0; mt < 2; mt++)
        #pragma unroll
        for (int nt = 0; nt < 8; nt++)
            #pragma unroll
            for (int e = 0; e < 4; e++) acc[mt][nt][e] = 0.f;

    // prologue: stages 0 and 1 (chunks 0,1 are always < two_nh)
    #pragma unroll
    for (int s = 0; s < 2; s++) {
        const int k0 = s * 32;
        const uint32_t dA = dA0 + s * STAGE_BYTES;
        const uint32_t dB = dB0 + s * STAGE_BYTES;
        cp16(dA, gA + k0); cp16(dA + 16, gA + k0 + 8);
        cp16(dB, gB + k0); cp16(dB + 16, gB + k0 + 8);
        CP_COMMIT();
    }

    int stage = 0, pstage = 2;
    for (int c = 0; c < nchunks; c++) {
        if (c + 1 == nchunks) { CP_WAIT(0); } else { CP_WAIT(1); }
        __syncthreads();

        if (c + 2 < nchunks) {
            const int c2 = c + 2;
            const int kA = ((c2 < two_nh) ? c2 : (c2 - two_nh)) * 32;
            const int kB = c2 * 32;
            const uint32_t dA = dA0 + pstage * STAGE_BYTES;
            const uint32_t dB = dB0 + pstage * STAGE_BYTES;
            cp16(dA, gA + kA); cp16(dA + 16, gA + kA + 8);
            cp16(dB, gB + kB); cp16(dB + 16, gB + kB + 8);
            CP_COMMIT();
            pstage = (pstage == 2) ? 0 : pstage + 1;
        }

        const uint32_t so = stage * STAGE_BYTES;
        #pragma unroll
        for (int ks = 0; ks < 2; ks++) {
            const uint32_t ko = so + ks * 32;     // 16 bf16 = 32 bytes
            uint32_t a[2][4], bq[4][4];
            LDSM4(a[0], aAddr[0] + ko);
            LDSM4(a[1], aAddr[1] + ko);
            LDSM4(bq[0], bAddr[0] + ko);
            LDSM4(bq[1], bAddr[1] + ko);
            LDSM4(bq[2], bAddr[2] + ko);
            LDSM4(bq[3], bAddr[3] + ko);
            #pragma unroll
            for (int mt = 0; mt < 2; mt++)
                #pragma unroll
                for (int nt = 0; nt < 8; nt++)
                    mma16816(acc[mt][nt], a[mt], &bq[nt >> 1][(nt & 1) * 2]);
        }
        stage = (stage == 2) ? 0 : stage + 1;
    }

    // ---- epilogue: registers -> global ----
    #pragma unroll
    for (int mt = 0; mt < 2; mt++) {
        #pragma unroll
        for (int half = 0; half < 2; half++) {
            const int r = row0 + wm * 32 + mt * 16 + g + half * 8;
            int i0 = 0, i1 = 0, i2 = 0;
            float w0 = 0.f, w1 = 0.f, w2 = 0.f;
            if (MODE == 1) {
                i0 = gidx[r * 3 + 0]; i1 = gidx[r * 3 + 1]; i2 = gidx[r * 3 + 2];
                w0 = gw[r * 3 + 0]; w1 = gw[r * 3 + 1]; w2 = gw[r * 3 + 2];
            }
            #pragma unroll
            for (int nt = 0; nt < 8; nt++) {
                const int ccol = col0 + wn * 64 + nt * 8 + 2 * t;
                float vx = acc[mt][nt][half * 2 + 0];
                float vy = acc[mt][nt][half * 2 + 1];
                if (MODE == 0) {
                    *(float2*)&outf[(size_t)r * C_HID + ccol] = make_float2(vx, vy);
                } else if (MODE == 2) {
                    float2 bb = *(const float2*)&bias[ccol];
                    vx = fmaxf(vx + bb.x, 0.f);
                    vy = fmaxf(vy + bb.y, 0.f);
                    *(float2*)&outf[(size_t)r * C_HID + ccol] = make_float2(vx, vy);
                } else {
                    float2 bb = *(const float2*)&bias[ccol];
                    float2 y0 = *(const float2*)&Y[(size_t)i0 * C_HID + ccol];
                    float2 y1 = *(const float2*)&Y[(size_t)i1 * C_HID + ccol];
                    float2 y2 = *(const float2*)&Y[(size_t)i2 * C_HID + ccol];
                    vx = fmaxf(vx + bb.x + w0 * y0.x + w1 * y1.x + w2 * y2.x, 0.f);
                    vy = fmaxf(vy + bb.y + w0 * y0.y + w1 * y1.y + w2 * y2.y, 0.f);
                    __nv_bfloat16 hx = __float2bfloat16(vx);
                    __nv_bfloat16 hy = __float2bfloat16(vy);
                    __nv_bfloat162 hi2 = __halves2bfloat162(hx, hy);
                    __nv_bfloat162 lo2 = __halves2bfloat162(
                        __float2bfloat16(vx - __bfloat162float(hx)),
                        __float2bfloat16(vy - __bfloat162float(hy)));
                    const size_t base = (size_t)r * (2 * C_HID) + ccol;
                    *(__nv_bfloat162*)&outh[base]         = hi2;
                    *(__nv_bfloat162*)&outh[base + C_HID] = lo2;
                }
            }
        }
    }
}

// batch_skip int32 -> float (tuple tail)
__global__ void cast_batch_kernel(const int* __restrict__ b, float* __restrict__ out, int n)
{
    int i = blockIdx.x * blockDim.x + threadIdx.x;
    if (i < n) out[i] = (float)b[i];
}

// ---------------------------------------------------------------------------
extern "C" void kernel_launch(void* const* d_in, const int* in_sizes, int n_in,
                              void* d_out, int out_size)
{
    (void)in_sizes; (void)n_in;
    const float* x        = (const float*)d_in[0];
    const float* pos      = (const float*)d_in[1];
    const float* x_skip   = (const float*)d_in[2];
    const float* pos_skip = (const float*)d_in[3];
    const float* W1       = (const float*)d_in[4];
    const float* b1       = (const float*)d_in[5];
    const float* W2       = (const float*)d_in[6];
    const float* b2       = (const float*)d_in[7];

    float *y, *w; int* idx;
    __nv_bfloat16 *xe, *xse, *h1e, *w1ae, *w1be, *w2e;
    cudaGetSymbolAddress((void**)&y,    g_y);
    cudaGetSymbolAddress((void**)&idx,  g_idx);
    cudaGetSymbolAddress((void**)&w,    g_w);
    cudaGetSymbolAddress((void**)&xe,   g_xe);
    cudaGetSymbolAddress((void**)&xse,  g_xse);
    cudaGetSymbolAddress((void**)&h1e,  g_h1e);
    cudaGetSymbolAddress((void**)&w1ae, g_w1ae);
    cudaGetSymbolAddress((void**)&w1be, g_w1be);
    cudaGetSymbolAddress((void**)&w2e,  g_w2e);

    static bool init_done = false;
    static cudaStream_t s_knn;
    static cudaEvent_t ev_fork, ev_join;
    if (!init_done) {
        cudaFuncSetAttribute(mma_gemm<0>, cudaFuncAttributeMaxDynamicSharedMemorySize, SM_BYTES);
        cudaFuncSetAttribute(mma_gemm<1>, cudaFuncAttributeMaxDynamicSharedMemorySize, SM_BYTES);
        cudaFuncSetAttribute(mma_gemm<2>, cudaFuncAttributeMaxDynamicSharedMemorySize, SM_BYTES);
        cudaStreamCreateWithFlags(&s_knn, cudaStreamNonBlocking);
        cudaEventCreateWithFlags(&ev_fork, cudaEventDisableTiming);
        cudaEventCreateWithFlags(&ev_join, cudaEventDisableTiming);
        init_done = true;
    }

    // fork: kNN on side stream, overlapped with expansions + GEMM1
    cudaEventRecord(ev_fork, 0);
    cudaStreamWaitEvent(s_knn, ev_fork, 0);
    knn_kernel<<<BATCH * (N_FINE / 128), 128, 0, s_knn>>>(pos, pos_skip, idx, w);
    cudaEventRecord(ev_join, s_knn);

    // main stream: expansions + GEMM1
    expand_act<<<(NC_TOT * C_IN / 2 + 255) / 256, 256>>>(x, xe, NC_TOT, C_IN);
    expand_act<<<(NF_TOT * C_SKIP / 2 + 255) / 256, 256>>>(x_skip, xse, NF_TOT, C_SKIP);
    expand_w_all<<<((C_IN + C_SKIP + C_HID) * C_HID + 255) / 256, 256>>>(
        W1, W2, w1ae, w1be, w2e);

    // GEMM1: y = x @ W1a    A [16384,512], B [256,768], 24 chunks, two_nh=16
    mma_gemm<0><<<dim3(2, NC_TOT / 128), 256, SM_BYTES>>>(
        xe, w1ae, nullptr, y, nullptr, 2 * C_IN, 3 * C_IN, (3 * C_IN) / 32,
        (2 * C_IN) / 32, nullptr, nullptr, nullptr);

    // join: GEMM2 needs kNN results
    cudaStreamWaitEvent(0, ev_join, 0);

    // GEMM2: h1 = relu(x_skip @ W1b + interp(y) + b1) -> [hi|lo] bf16 h1e
    mma_gemm<1><<<dim3(2, NF_TOT / 128), 256, SM_BYTES>>>(
        xse, w1be, b1, nullptr, h1e, 2 * C_SKIP, 3 * C_SKIP, (3 * C_SKIP) / 32,
        (2 * C_SKIP) / 32, y, idx, w);

    // GEMM3: out = relu(h1 @ W2 + b2) -> fp32 d_out
    mma_gemm<2><<<dim3(2, NF_TOT / 128), 256, SM_BYTES>>>(
        h1e, w2e, b2, (float*)d_out, nullptr, 2 * C_HID, 3 * C_HID, (3 * C_HID) / 32,
        (2 * C_HID) / 32, nullptr, nullptr, nullptr);

    // Tuple tail: (h, pos_skip, batch_skip) — append if the harness expects it
    const long long H_ELEMS   = (long long)NF_TOT * C_HID;
    const long long POS_ELEMS = (long long)NF_TOT * 3;
    if ((long long)out_size >= H_ELEMS + POS_ELEMS) {
        cudaMemcpyAsync((float*)d_out + H_ELEMS, pos_skip,
                        POS_ELEMS * sizeof(float), cudaMemcpyDeviceToDevice);
    }
    if ((long long)out_size >= H_ELEMS + POS_ELEMS + NF_TOT) {
        const int* batch_skip = (const int*)d_in[9];
        cast_batch_kernel<<<(NF_TOT + 255) / 256, 256>>>(
            batch_skip, (float*)d_out + H_ELEMS + POS_ELEMS, NF_TOT);
    }
}

// round 7
// speedup vs baseline: 1.3025x; 1.0682x over previous
#include <cuda_runtime.h>
#include <cuda_bf16.h>
#include <cstdint>

#define BATCH    16
#define N_COARSE 1024
#define N_FINE   4096
#define C_IN     256
#define C_SKIP   128
#define C_HID    256
#define NC_TOT   (BATCH * N_COARSE)   // 16384
#define NF_TOT   (BATCH * N_FINE)     // 65536

// ---------------- scratch (static device globals; no runtime alloc) --------
__device__ float          g_y[NC_TOT * C_HID];                 // 16 MB fp32
__device__ int            g_idx[NF_TOT * 3];
__device__ float          g_w[NF_TOT * 3];
__device__ __nv_bfloat16  g_xe[NC_TOT * 2 * C_IN];             // [16384, 512]  [hi|lo]
__device__ __nv_bfloat16  g_xse[NF_TOT * 2 * C_SKIP];          // [65536, 256]  [hi|lo]
__device__ __nv_bfloat16  g_h1e[(size_t)NF_TOT * 2 * C_HID];   // [65536, 512]  [hi|lo]
__device__ __nv_bfloat16  g_w1ae[C_HID * 3 * C_IN];            // [256 n, 768 k] [hi|hi|lo]
__device__ __nv_bfloat16  g_w1be[C_HID * 3 * C_SKIP];          // [256 n, 384 k]
__device__ __nv_bfloat16  g_w2e[C_HID * 3 * C_HID];            // [256 n, 768 k]

// ---------------- PTX helpers (portable, no arch-gated features) -----------
__device__ __forceinline__ uint32_t smem_u32(const void* p) {
    return (uint32_t)__cvta_generic_to_shared(p);
}
__device__ __forceinline__ void cp16(uint32_t dst, const void* src) {
    asm volatile("cp.async.cg.shared.global [%0], [%1], 16;" :: "r"(dst), "l"(src));
}
#define CP_COMMIT()  asm volatile("cp.async.commit_group;" ::: "memory")
#define CP_WAIT(n)   asm volatile("cp.async.wait_group %0;" :: "n"(n) : "memory")
#define LDSM4(r, addr) \
    asm volatile("ldmatrix.sync.aligned.m8n8.x4.shared.b16 {%0,%1,%2,%3}, [%4];" \
        : "=r"((r)[0]), "=r"((r)[1]), "=r"((r)[2]), "=r"((r)[3]) : "r"(addr))

__device__ __forceinline__ void mma16816(float* c, const uint32_t* a, const uint32_t* b) {
    asm volatile(
        "mma.sync.aligned.m16n8k16.row.col.f32.bf16.bf16.f32 "
        "{%0,%1,%2,%3}, {%4,%5,%6,%7}, {%8,%9}, {%0,%1,%2,%3};"
        : "+f"(c[0]), "+f"(c[1]), "+f"(c[2]), "+f"(c[3])
        : "r"(a[0]), "r"(a[1]), "r"(a[2]), "r"(a[3]), "r"(b[0]), "r"(b[1]));
}

// ---------------- kNN (k=3): 1 point/thread, float4 smem --------------------
__global__ __launch_bounds__(128) void knn_kernel(
    const float* __restrict__ pos, const float* __restrict__ pos_skip,
    int* __restrict__ gidx, float* __restrict__ gw)
{
    __shared__ float4 sp[N_COARSE];   // 16 KB
    const int chunks = N_FINE / 128;              // 32
    const int b = blockIdx.x / chunks;
    const int chunk = blockIdx.x % chunks;
    const int tid = threadIdx.x;

    const float* pc = pos + (size_t)b * N_COARSE * 3;
    for (int i = tid; i < N_COARSE; i += 128)
        sp[i] = make_float4(pc[i * 3 + 0], pc[i * 3 + 1], pc[i * 3 + 2], 0.f);
    __syncthreads();

    const int f = b * N_FINE + chunk * 128 + tid;
    const float px = pos_skip[f * 3 + 0];
    const float py = pos_skip[f * 3 + 1];
    const float pz = pos_skip[f * 3 + 2];

    float d0 = 3.4e38f, d1 = 3.4e38f, d2 = 3.4e38f;
    int i0 = 0, i1 = 0, i2 = 0;
    #pragma unroll 4
    for (int j = 0; j < N_COARSE; j++) {
        float4 p = sp[j];
        float dx = px - p.x, dy = py - p.y, dz = pz - p.z;
        float d = dx * dx + dy * dy + dz * dz;
        if (d < d2) {
            if (d < d1) {
                d2 = d1; i2 = i1;
                if (d < d0) { d1 = d0; i1 = i0; d0 = d; i0 = j; }
                else        { d1 = d;  i1 = j; }
            } else { d2 = d; i2 = j; }
        }
    }
    float w0 = 1.0f / fmaxf(d0, 1e-16f);
    float w1 = 1.0f / fmaxf(d1, 1e-16f);
    float w2 = 1.0f / fmaxf(d2, 1e-16f);
    float inv = 1.0f / (w0 + w1 + w2);
    gidx[f * 3 + 0] = b * N_COARSE + i0;
    gidx[f * 3 + 1] = b * N_COARSE + i1;
    gidx[f * 3 + 2] = b * N_COARSE + i2;
    gw[f * 3 + 0] = w0 * inv;
    gw[f * 3 + 1] = w1 * inv;
    gw[f * 3 + 2] = w2 * inv;
}

// ---------------- split-bf16 expansion --------------------------------------
// activations: [M,K] fp32 -> [M,2K] bf16 segments [hi | lo] (vectorized x2)
__global__ void expand_act(const float* __restrict__ in, __nv_bfloat16* __restrict__ out,
                           int M, int K)
{
    int i = blockIdx.x * blockDim.x + threadIdx.x;      // pair index
    int tot = M * (K / 2);
    if (i >= tot) return;
    int kh = K / 2;
    int m = i / kh, kp = i - m * kh;
    float2 v = *(const float2*)(in + (size_t)m * K + kp * 2);
    __nv_bfloat16 hx = __float2bfloat16(v.x), hy = __float2bfloat16(v.y);
    __nv_bfloat162 hi2 = __halves2bfloat162(hx, hy);
    __nv_bfloat162 lo2 = __halves2bfloat162(
        __float2bfloat16(v.x - __bfloat162float(hx)),
        __float2bfloat16(v.y - __bfloat162float(hy)));
    __nv_bfloat16* o = out + (size_t)m * 2 * K + kp * 2;
    *(__nv_bfloat162*)(o)     = hi2;
    *(__nv_bfloat162*)(o + K) = lo2;
}
// all weights in one launch; output transposed [N, 3K] bf16, segs [hi|hi|lo]
__global__ void expand_w_all(const float* __restrict__ W1, const float* __restrict__ W2,
                             __nv_bfloat16* __restrict__ w1ae,
                             __nv_bfloat16* __restrict__ w1be,
                             __nv_bfloat16* __restrict__ w2e)
{
    int i = blockIdx.x * blockDim.x + threadIdx.x;
    const int TOT1 = (C_IN + C_SKIP) * C_HID;     // 98304
    const int TOT2 = C_HID * C_HID;               // 65536
    if (i >= TOT1 + TOT2) return;
    float v; __nv_bfloat16* o; int K, k, n;
    if (i < TOT1) {
        k = i / C_HID; n = i - k * C_HID;
        v = W1[i];
        if (k < C_IN) { K = C_IN; o = w1ae + (size_t)n * 3 * K; }
        else          { K = C_SKIP; k -= C_IN; o = w1be + (size_t)n * 3 * K; }
    } else {
        int j = i - TOT1;
        k = j / C_HID; n = j - k * C_HID;
        v = W2[j];
        K = C_HID; o = w2e + (size_t)n * 3 * K;
    }
    __nv_bfloat16 hi = __float2bfloat16(v);
    __nv_bfloat16 lo = __float2bfloat16(v - __bfloat162float(hi));
    o[k] = hi; o[K + k] = hi; o[2 * K + k] = lo;
}

// ---------------- HMMA GEMM (4-stage cp.async + ldmatrix, unrolled) --------
// C[128,128] per CTA.  A:[M,LDA] bf16 [hi|lo] (hi re-read for 3rd segment),
// Bw:[N,LDB] bf16 [hi|hi|lo].  256 thr = 8 warps (4x2); warp 32x64; BK=32.
// All loop trip counts and strides are compile-time constants.
#define PITCH 40                        // bf16 per smem row (80B)
#define OP_BYTES (128 * PITCH * 2)      // 10240 per operand per stage
#define STAGE_BYTES (2 * OP_BYTES)      // 20480
#define NSTAGE 4
#define SM_BYTES (NSTAGE * STAGE_BYTES) // 81920

template <int MODE, int NCHUNKS, int TWO_NH, int LDA, int LDB>
__global__ __launch_bounds__(256, 2) void mma_gemm(
    const __nv_bfloat16* __restrict__ A, const __nv_bfloat16* __restrict__ Bw,
    const float* __restrict__ bias, float* __restrict__ outf,
    __nv_bfloat16* __restrict__ outh,
    const float* __restrict__ Y, const int* __restrict__ gidx,
    const float* __restrict__ gw)
{
    extern __shared__ __align__(16) char smem[];
    const uint32_t sb = smem_u32(smem);

    const int tid = threadIdx.x;
    const int wid = tid >> 5, lane = tid & 31;
    const int g = lane >> 2, t = lane & 3;
    const int wm = wid & 3, wn = wid >> 2;        // 4 x 2 warp grid
    const int row0 = blockIdx.y * 128, col0 = blockIdx.x * 128;

    // cp.async loader: 128 rows x 32 bf16 (64B) per operand per stage
    const int lrow = tid >> 1;                    // 0..127
    const int lch  = (tid & 1) * 2;               // 16B-chunk 0 or 2
    const uint32_t dA0 = sb + (uint32_t)(lrow * 80 + lch * 16);
    const uint32_t dB0 = dA0 + OP_BYTES;
    const __nv_bfloat16* gA = A + (size_t)(row0 + lrow) * LDA + lch * 8;
    const __nv_bfloat16* gB = Bw + (size_t)(col0 + lrow) * LDB + lch * 8;

    // ldmatrix base addresses (stage 0)
    uint32_t aAddr[2], bAddr[4];
    #pragma unroll
    for (int mt = 0; mt < 2; mt++)
        aAddr[mt] = sb + (uint32_t)(((wm * 32 + mt * 16 + (lane & 15)) * PITCH
                                     + (lane >> 4) * 8) * 2);
    #pragma unroll
    for (int p = 0; p < 4; p++)
        bAddr[p] = sb + OP_BYTES + (uint32_t)(((wn * 64 + p * 16 + (lane & 7)
                                     + ((lane >> 4) & 1) * 8) * PITCH
                                     + ((lane >> 3) & 1) * 8) * 2);

    float acc[2][8][4];
    #pragma unroll
    for (int mt = 0; mt < 2; mt++)
        #pragma unroll
        for (int nt = 0; nt < 8; nt++)
            #pragma unroll
            for (int e = 0; e < 4; e++) acc[mt][nt][e] = 0.f;

    // prologue: stages 0..2 (chunks 0..2 always < TWO_NH for our sizes)
    #pragma unroll
    for (int s = 0; s < NSTAGE - 1; s++) {
        const int kA = ((s < TWO_NH) ? s : (s - TWO_NH)) * 32;
        const uint32_t dA = dA0 + s * STAGE_BYTES;
        const uint32_t dB = dB0 + s * STAGE_BYTES;
        cp16(dA, gA + kA); cp16(dA + 16, gA + kA + 8);
        cp16(dB, gB + s * 32); cp16(dB + 16, gB + s * 32 + 8);
        CP_COMMIT();
    }

    #pragma unroll
    for (int c = 0; c < NCHUNKS; c++) {
        // wait for chunk c: allowed pending = min(NSTAGE-2, NCHUNKS-1-c)
        if (c + (NSTAGE - 1) <= NCHUNKS) { CP_WAIT(NSTAGE - 2); }
        else if (c + 2 == NCHUNKS)       { CP_WAIT(1); }
        else                             { CP_WAIT(0); }
        __syncthreads();

        if (c + NSTAGE - 1 < NCHUNKS) {
            const int c2 = c + NSTAGE - 1;
            const int kA = ((c2 < TWO_NH) ? c2 : (c2 - TWO_NH)) * 32;
            const int kB = c2 * 32;
            const uint32_t dA = dA0 + (c2 % NSTAGE) * STAGE_BYTES;
            const uint32_t dB = dB0 + (c2 % NSTAGE) * STAGE_BYTES;
            cp16(dA, gA + kA); cp16(dA + 16, gA + kA + 8);
            cp16(dB, gB + kB); cp16(dB + 16, gB + kB + 8);
            CP_COMMIT();
        }

        const uint32_t so = (c % NSTAGE) * STAGE_BYTES;
        #pragma unroll
        for (int ks = 0; ks < 2; ks++) {
            const uint32_t ko = so + ks * 32;     // 16 bf16 = 32 bytes
            uint32_t a[2][4], bq[4][4];
            LDSM4(a[0], aAddr[0] + ko);
            LDSM4(a[1], aAddr[1] + ko);
            LDSM4(bq[0], bAddr[0] + ko);
            LDSM4(bq[1], bAddr[1] + ko);
            LDSM4(bq[2], bAddr[2] + ko);
            LDSM4(bq[3], bAddr[3] + ko);
            #pragma unroll
            for (int mt = 0; mt < 2; mt++)
                #pragma unroll
                for (int nt = 0; nt < 8; nt++)
                    mma16816(acc[mt][nt], a[mt], &bq[nt >> 1][(nt & 1) * 2]);
        }
    }

    // ---- epilogue: registers -> global ----
    #pragma unroll
    for (int mt = 0; mt < 2; mt++) {
        #pragma unroll
        for (int half = 0; half < 2; half++) {
            const int r = row0 + wm * 32 + mt * 16 + g + half * 8;
            int i0 = 0, i1 = 0, i2 = 0;
            float w0 = 0.f, w1 = 0.f, w2 = 0.f;
            if (MODE == 1) {
                i0 = gidx[r * 3 + 0]; i1 = gidx[r * 3 + 1]; i2 = gidx[r * 3 + 2];
                w0 = gw[r * 3 + 0]; w1 = gw[r * 3 + 1]; w2 = gw[r * 3 + 2];
            }
            #pragma unroll
            for (int nt = 0; nt < 8; nt++) {
                const int ccol = col0 + wn * 64 + nt * 8 + 2 * t;
                float vx = acc[mt][nt][half * 2 + 0];
                float vy = acc[mt][nt][half * 2 + 1];
                if (MODE == 0) {
                    *(float2*)&outf[(size_t)r * C_HID + ccol] = make_float2(vx, vy);
                } else if (MODE == 2) {
                    float2 bb = *(const float2*)&bias[ccol];
                    vx = fmaxf(vx + bb.x, 0.f);
                    vy = fmaxf(vy + bb.y, 0.f);
                    *(float2*)&outf[(size_t)r * C_HID + ccol] = make_float2(vx, vy);
                } else {
                    float2 bb = *(const float2*)&bias[ccol];
                    float2 y0 = *(const float2*)&Y[(size_t)i0 * C_HID + ccol];
                    float2 y1 = *(const float2*)&Y[(size_t)i1 * C_HID + ccol];
                    float2 y2 = *(const float2*)&Y[(size_t)i2 * C_HID + ccol];
                    vx = fmaxf(vx + bb.x + w0 * y0.x + w1 * y1.x + w2 * y2.x, 0.f);
                    vy = fmaxf(vy + bb.y + w0 * y0.y + w1 * y1.y + w2 * y2.y, 0.f);
                    __nv_bfloat16 hx = __float2bfloat16(vx);
                    __nv_bfloat16 hy = __float2bfloat16(vy);
                    __nv_bfloat162 hi2 = __halves2bfloat162(hx, hy);
                    __nv_bfloat162 lo2 = __halves2bfloat162(
                        __float2bfloat16(vx - __bfloat162float(hx)),
                        __float2bfloat16(vy - __bfloat162float(hy)));
                    const size_t base = (size_t)r * (2 * C_HID) + ccol;
                    *(__nv_bfloat162*)&outh[base]         = hi2;
                    *(__nv_bfloat162*)&outh[base + C_HID] = lo2;
                }
            }
        }
    }
}

// batch_skip int32 -> float (tuple tail)
__global__ void cast_batch_kernel(const int* __restrict__ b, float* __restrict__ out, int n)
{
    int i = blockIdx.x * blockDim.x + threadIdx.x;
    if (i < n) out[i] = (float)b[i];
}

// ---------------------------------------------------------------------------
extern "C" void kernel_launch(void* const* d_in, const int* in_sizes, int n_in,
                              void* d_out, int out_size)
{
    (void)in_sizes; (void)n_in;
    const float* x        = (const float*)d_in[0];
    const float* pos      = (const float*)d_in[1];
    const float* x_skip   = (const float*)d_in[2];
    const float* pos_skip = (const float*)d_in[3];
    const float* W1       = (const float*)d_in[4];
    const float* b1       = (const float*)d_in[5];
    const float* W2       = (const float*)d_in[6];
    const float* b2       = (const float*)d_in[7];

    float *y, *w; int* idx;
    __nv_bfloat16 *xe, *xse, *h1e, *w1ae, *w1be, *w2e;
    cudaGetSymbolAddress((void**)&y,    g_y);
    cudaGetSymbolAddress((void**)&idx,  g_idx);
    cudaGetSymbolAddress((void**)&w,    g_w);
    cudaGetSymbolAddress((void**)&xe,   g_xe);
    cudaGetSymbolAddress((void**)&xse,  g_xse);
    cudaGetSymbolAddress((void**)&h1e,  g_h1e);
    cudaGetSymbolAddress((void**)&w1ae, g_w1ae);
    cudaGetSymbolAddress((void**)&w1be, g_w1be);
    cudaGetSymbolAddress((void**)&w2e,  g_w2e);

    auto k1 = mma_gemm<0, 24, 16, 512, 768>;
    auto k2 = mma_gemm<1, 12,  8, 256, 384>;
    auto k3 = mma_gemm<2, 24, 16, 512, 768>;

    static bool init_done = false;
    static cudaStream_t s_knn;
    static cudaEvent_t ev_fork, ev_join;
    if (!init_done) {
        cudaFuncSetAttribute(k1, cudaFuncAttributeMaxDynamicSharedMemorySize, SM_BYTES);
        cudaFuncSetAttribute(k2, cudaFuncAttributeMaxDynamicSharedMemorySize, SM_BYTES);
        cudaFuncSetAttribute(k3, cudaFuncAttributeMaxDynamicSharedMemorySize, SM_BYTES);
        cudaStreamCreateWithFlags(&s_knn, cudaStreamNonBlocking);
        cudaEventCreateWithFlags(&ev_fork, cudaEventDisableTiming);
        cudaEventCreateWithFlags(&ev_join, cudaEventDisableTiming);
        init_done = true;
    }

    // fork: kNN + x_skip expansion on side stream (only GEMM2 consumes them)
    cudaEventRecord(ev_fork, 0);
    cudaStreamWaitEvent(s_knn, ev_fork, 0);
    knn_kernel<<<BATCH * (N_FINE / 128), 128, 0, s_knn>>>(pos, pos_skip, idx, w);
    expand_act<<<(NF_TOT * C_SKIP / 2 + 255) / 256, 256, 0, s_knn>>>(
        x_skip, xse, NF_TOT, C_SKIP);
    cudaEventRecord(ev_join, s_knn);

    // main stream: expansions + GEMM1
    expand_act<<<(NC_TOT * C_IN / 2 + 255) / 256, 256>>>(x, xe, NC_TOT, C_IN);
    expand_w_all<<<((C_IN + C_SKIP + C_HID) * C_HID + 255) / 256, 256>>>(
        W1, W2, w1ae, w1be, w2e);

    // GEMM1: y = x @ W1a
    k1<<<dim3(2, NC_TOT / 128), 256, SM_BYTES>>>(
        xe, w1ae, nullptr, y, nullptr, nullptr, nullptr, nullptr);

    // join: GEMM2 needs kNN results + xse
    cudaStreamWaitEvent(0, ev_join, 0);

    // GEMM2: h1 = relu(x_skip @ W1b + interp(y) + b1) -> [hi|lo] bf16 h1e
    k2<<<dim3(2, NF_TOT / 128), 256, SM_BYTES>>>(
        xse, w1be, b1, nullptr, h1e, y, idx, w);

    // GEMM3: out = relu(h1 @ W2 + b2) -> fp32 d_out
    k3<<<dim3(2, NF_TOT / 128), 256, SM_BYTES>>>(
        h1e, w2e, b2, (float*)d_out, nullptr, nullptr, nullptr, nullptr);

    // Tuple tail: (h, pos_skip, batch_skip) — append if the harness expects it
    const long long H_ELEMS   = (long long)NF_TOT * C_HID;
    const long long POS_ELEMS = (long long)NF_TOT * 3;
    if ((long long)out_size >= H_ELEMS + POS_ELEMS) {
        cudaMemcpyAsync((float*)d_out + H_ELEMS, pos_skip,
                        POS_ELEMS * sizeof(float), cudaMemcpyDeviceToDevice);
    }
    if ((long long)out_size >= H_ELEMS + POS_ELEMS + NF_TOT) {
        const int* batch_skip = (const int*)d_in[9];
        cast_batch_kernel<<<(NF_TOT + 255) / 256, 256>>>(
            batch_skip, (float*)d_out + H_ELEMS + POS_ELEMS, NF_TOT);
    }
}